// round 1
// baseline (speedup 1.0000x reference)
#include <cuda_runtime.h>
#include <cstdint>

#define T_CYCLES 256
#define WL_CAP (1 << 20)   // worklist capacity (N expected 524288)

__device__ int g_count;
__device__ unsigned g_worklist[WL_CAP];

__global__ void zero_counter_kernel() { g_count = 0; }

// Pass 1: per-stream total bit count + t=256 stability check.
// 4 streams per thread via int4 loads (perfectly coalesced, 512B/warp/iter).
__global__ void __launch_bounds__(256) pass1_kernel(
    const float* __restrict__ src,
    const int4*  __restrict__ bits4,
    float*       __restrict__ out,
    int n4)
{
    int i = blockIdx.x * blockDim.x + threadIdx.x;
    bool valid = (i < n4);

    int c0 = 0, c1 = 0, c2 = 0, c3 = 0;
    bool needy[4] = {false, false, false, false};
    int cv[4] = {0, 0, 0, 0};

    if (valid) {
        const int4* p = bits4 + i;
        // Pairwise accumulation -> IADD3 (2 bits/instr), unroll for MLP=8 LDG.128
        #pragma unroll 4
        for (int t = 0; t < T_CYCLES; t += 2) {
            int4 a = __ldcs(p + (size_t)t       * n4);
            int4 b = __ldcs(p + (size_t)(t + 1) * n4);
            c0 += a.x + b.x;
            c1 += a.y + b.y;
            c2 += a.z + b.z;
            c3 += a.w + b.w;
        }
        float4 s4 = ((const float4*)src)[i];
        float sv[4] = {s4.x, s4.y, s4.z, s4.w};
        cv[0] = c0; cv[1] = c1; cv[2] = c2; cv[3] = c3;
        #pragma unroll
        for (int j = 0; j < 4; j++) {
            float s = fminf(fmaxf(sv[j], -1.0f), 1.0f);
            // pp = cnt/256 (exact); pp*2-1 == cnt*(1/128)-1 (exact); pe rounds once,
            // identical to reference rounding.
            float pe = (float)cv[j] * (1.0f / 128.0f) - 1.0f - s;
            bool unstable = fabsf(pe) > 0.05f;
            if (unstable) {
                out[4 * i + j] = 0.0f;     // cts = 256 -> stability = 0
            } else {
                needy[j] = true;           // needs backward scan in pass 2
            }
        }
    }

    // Warp-aggregated worklist push (1 atomic per warp)
    const unsigned FULL = 0xffffffffu;
    int lane = threadIdx.x & 31;
    int m = (int)needy[0] + (int)needy[1] + (int)needy[2] + (int)needy[3];
    int sc = m;
    #pragma unroll
    for (int d = 1; d < 32; d <<= 1) {
        int v = __shfl_up_sync(FULL, sc, d);
        if (lane >= d) sc += v;
    }
    int tot = __shfl_sync(FULL, sc, 31);
    int base = 0;
    if (lane == 31 && tot > 0) base = atomicAdd(&g_count, tot);
    base = __shfl_sync(FULL, base, 31);
    int pos = base + sc - m;   // exclusive prefix
    #pragma unroll
    for (int j = 0; j < 4; j++) {
        if (needy[j] && pos < WL_CAP) {
            // pack: total (<=256, 9 bits) in high bits, stream index in low 23
            g_worklist[pos++] = ((unsigned)cv[j] << 23) | (unsigned)(4 * i + j);
        }
    }
}

// Pass 2: warp per needy stream. Backward scan t=255..1 in 32-wide chunks.
// cnt_t = cnt_{t_hi+1} - (inclusive lane suffix of bits[row t..t_hi]).
__global__ void __launch_bounds__(256) pass2_kernel(
    const float* __restrict__ src,
    const int*   __restrict__ bits,
    float*       __restrict__ out,
    int N)
{
    const unsigned FULL = 0xffffffffu;
    int warpsPerBlock = blockDim.x >> 5;
    int wg = blockIdx.x * warpsPerBlock + (threadIdx.x >> 5);
    int nw = gridDim.x * warpsPerBlock;
    int lane = threadIdx.x & 31;
    int cnt = g_count;

    for (int w = wg; w < cnt; w += nw) {
        unsigned e = g_worklist[w];
        int n = (int)(e & 0x7FFFFFu);
        int total = (int)(e >> 23);
        float s = fminf(fmaxf(src[n], -1.0f), 1.0f);

        int base = total;                         // cnt_{256}
        float result = 1.0f - (1.0f / 256.0f);    // cts=0 -> clip to 1
        int t_hi = 255;

        #pragma unroll 1
        for (int ch = 0; ch < 8; ch++) {
            int t = t_hi - lane;                  // descending t per lane
            int b = (t >= 1) ? bits[(size_t)t * N + n] : 0;
            int suf = b;                          // inclusive scan over lanes
            #pragma unroll
            for (int d = 1; d < 32; d <<= 1) {
                int v = __shfl_up_sync(FULL, suf, d);
                if (lane >= d) suf += v;
            }
            int cnt_t = base - suf;
            bool unstable = false;
            if (t >= 1) {
                float pp = __fdiv_rn((float)cnt_t, (float)t);  // IEEE div, matches ref
                float pe = (pp * 2.0f - 1.0f) - s;
                unstable = fabsf(pe) > 0.05f;
            }
            unsigned mset = __ballot_sync(FULL, unstable);
            if (mset) {
                int l = __ffs(mset) - 1;          // lowest lane = largest t
                int cts = t_hi - l;
                result = 1.0f - (float)cts * (1.0f / 256.0f);
                break;
            }
            base -= __shfl_sync(FULL, suf, 31);
            t_hi -= 32;
        }
        if (lane == 0) out[n] = result;
    }
}

extern "C" void kernel_launch(void* const* d_in, const int* in_sizes, int n_in,
                              void* d_out, int out_size)
{
    const float* src  = (const float*)d_in[0];
    const int*   bits = (const int*)d_in[1];
    float*       out  = (float*)d_out;
    int N  = in_sizes[0];
    int n4 = N / 4;

    zero_counter_kernel<<<1, 1>>>();
    pass1_kernel<<<(n4 + 255) / 256, 256>>>(src, (const int4*)bits, out, n4);
    pass2_kernel<<<296, 256>>>(src, bits, out, N);
}